// round 1
// baseline (speedup 1.0000x reference)
#include <cuda_runtime.h>
#include <math.h>

#define HIDDEN   256
#define MAXLEN   256
#define NLAYERS  4
#define VOCAB    50257

// ---------------- scratch (device globals; no allocation allowed) ----------
__device__ float g_attn_in[2 * HIDDEN];      // [embedded, hidden0]
__device__ float g_attn_logits[MAXLEN];
__device__ float g_comb_in[2 * HIDDEN];      // [embedded, attn_applied]
__device__ float g_x[HIDDEN];                // current layer input / output
__device__ float g_gates[6 * HIDDEN];        // gi[0:768], gh[768:1536]
__device__ float g_blockmax[8192];
__device__ float g_partsum[256];
__device__ float g_gmax;
__device__ float g_lse;

// ---------------- stage 1: embed + build attn_in ---------------------------
__global__ void k_prep(const int* __restrict__ token,
                       const float* __restrict__ hidden,
                       const float* __restrict__ emb) {
    int t = threadIdx.x;
    int tok = token[0];
    float e = emb[(size_t)tok * HIDDEN + t];
    g_attn_in[t]          = e;
    g_attn_in[HIDDEN + t] = hidden[t];   // hidden[0,0,:]
    g_comb_in[t]          = e;
}

// ---------------- generic warp-per-row matvec (COLS = 256 or 512) ----------
template <int COLS, bool RELU>
__global__ void k_matvec(const float* __restrict__ W,
                         const float* __restrict__ b,
                         const float* __restrict__ v,
                         float* __restrict__ y, int rows) {
    int wid = threadIdx.x >> 5, lane = threadIdx.x & 31;
    int row = blockIdx.x * 8 + wid;
    if (row >= rows) return;
    const float4* Wr = (const float4*)(W + (size_t)row * COLS);
    const float4* V  = (const float4*)v;
    float s = 0.f;
#pragma unroll
    for (int c = 0; c < COLS / 128; c++) {
        float4 w4 = Wr[lane + c * 32];
        float4 v4 = V[lane + c * 32];
        s += w4.x * v4.x + w4.y * v4.y + w4.z * v4.z + w4.w * v4.w;
    }
#pragma unroll
    for (int o = 16; o; o >>= 1) s += __shfl_down_sync(0xffffffffu, s, o);
    if (lane == 0) {
        s += b[row];
        y[row] = RELU ? fmaxf(s, 0.f) : s;
    }
}

// ---------------- stage 3: softmax over 256 + attn_applied + comb_in -------
__global__ void k_attn_post(const float* __restrict__ enc,
                            float* __restrict__ out_attnw) {
    __shared__ float sw[MAXLEN];
    __shared__ float red[MAXLEN];
    int t = threadIdx.x;
    float v = g_attn_logits[t];
    red[t] = v; __syncthreads();
    for (int s = 128; s; s >>= 1) {
        if (t < s) red[t] = fmaxf(red[t], red[t + s]);
        __syncthreads();
    }
    float m = red[0]; __syncthreads();
    float e = expf(v - m);
    red[t] = e; __syncthreads();
    for (int s = 128; s; s >>= 1) {
        if (t < s) red[t] += red[t + s];
        __syncthreads();
    }
    float w = e / red[0];
    sw[t] = w;
    out_attnw[t] = w;
    __syncthreads();
    float a = 0.f;
    for (int l = 0; l < MAXLEN; l++) a += sw[l] * enc[l * HIDDEN + t];
    g_comb_in[HIDDEN + t] = a;
}

// ---------------- GRU matvec: 1536 rows (gi then gh), warp per row ---------
__global__ void k_gru_mv(const float* __restrict__ wih,
                         const float* __restrict__ whh,
                         const float* __restrict__ bih,
                         const float* __restrict__ bhh,
                         const float* __restrict__ hidden_in, int l) {
    int wid = threadIdx.x >> 5, lane = threadIdx.x & 31;
    int row = blockIdx.x * 8 + wid;           // 0..1535
    const float* W; const float* v; float bias;
    if (row < 3 * HIDDEN) {
        W = wih + ((size_t)l * 3 * HIDDEN + row) * HIDDEN;
        v = g_x;
        bias = bih[l * 3 * HIDDEN + row];
    } else {
        int r = row - 3 * HIDDEN;
        W = whh + ((size_t)l * 3 * HIDDEN + r) * HIDDEN;
        v = hidden_in + l * HIDDEN;
        bias = bhh[l * 3 * HIDDEN + r];
    }
    const float4* Wr = (const float4*)W;
    const float4* V  = (const float4*)v;
    float s = 0.f;
#pragma unroll
    for (int c = 0; c < 2; c++) {
        float4 w4 = Wr[lane + c * 32];
        float4 v4 = V[lane + c * 32];
        s += w4.x * v4.x + w4.y * v4.y + w4.z * v4.z + w4.w * v4.w;
    }
#pragma unroll
    for (int o = 16; o; o >>= 1) s += __shfl_down_sync(0xffffffffu, s, o);
    if (lane == 0) g_gates[row] = s + bias;
}

// ---------------- GRU gate combine (single block) ---------------------------
__global__ void k_gru_combine(const float* __restrict__ hidden_in, int l,
                              float* __restrict__ out_hidden) {
    int t = threadIdx.x;
    float ir = g_gates[t], iz = g_gates[HIDDEN + t], in_ = g_gates[2 * HIDDEN + t];
    float hr = g_gates[3 * HIDDEN + t], hz = g_gates[4 * HIDDEN + t], hn = g_gates[5 * HIDDEN + t];
    float r = 1.f / (1.f + expf(-(ir + hr)));
    float z = 1.f / (1.f + expf(-(iz + hz)));
    float n = tanhf(in_ + r * hn);
    float hp = hidden_in[l * HIDDEN + t];
    float h = (1.f - z) * n + z * hp;
    out_hidden[l * HIDDEN + t] = h;
    g_x[t] = h;
}

// ---------------- vocab logits: warp per row + per-block max ---------------
__global__ void k_logits(const float* __restrict__ out_w,
                         const float* __restrict__ out_b,
                         float* __restrict__ logits) {
    __shared__ float sx[HIDDEN];
    __shared__ float smax[8];
    int t = threadIdx.x, wid = t >> 5, lane = t & 31;
    sx[t] = g_x[t];
    __syncthreads();
    int row = blockIdx.x * 8 + wid;
    float val = -INFINITY;
    if (row < VOCAB) {
        const float4* Wr = (const float4*)(out_w + (size_t)row * HIDDEN);
        const float4* V  = (const float4*)sx;
        float s = 0.f;
#pragma unroll
        for (int c = 0; c < 2; c++) {
            float4 w4 = Wr[lane + c * 32];
            float4 v4 = V[lane + c * 32];
            s += w4.x * v4.x + w4.y * v4.y + w4.z * v4.z + w4.w * v4.w;
        }
#pragma unroll
        for (int o = 16; o; o >>= 1) s += __shfl_down_sync(0xffffffffu, s, o);
        if (lane == 0) {
            s += out_b[row];
            logits[row] = s;
            val = s;
        }
    }
    if (lane == 0) smax[wid] = val;
    __syncthreads();
    if (t == 0) {
        float m = smax[0];
#pragma unroll
        for (int i = 1; i < 8; i++) m = fmaxf(m, smax[i]);
        g_blockmax[blockIdx.x] = m;
    }
}

__global__ void k_red_max(int nblocks) {
    __shared__ float red[256];
    int t = threadIdx.x;
    float m = -INFINITY;
    for (int i = t; i < nblocks; i += 256) m = fmaxf(m, g_blockmax[i]);
    red[t] = m; __syncthreads();
    for (int s = 128; s; s >>= 1) {
        if (t < s) red[t] = fmaxf(red[t], red[t + s]);
        __syncthreads();
    }
    if (t == 0) g_gmax = red[0];
}

__global__ void k_sumexp(const float* __restrict__ logits) {
    __shared__ float red[256];
    int t = threadIdx.x;
    float gm = g_gmax;
    float s = 0.f;
    for (int i = blockIdx.x * blockDim.x + t; i < VOCAB; i += gridDim.x * blockDim.x)
        s += expf(logits[i] - gm);
    red[t] = s; __syncthreads();
    for (int st = 128; st; st >>= 1) {
        if (t < st) red[t] += red[t + st];
        __syncthreads();
    }
    if (t == 0) g_partsum[blockIdx.x] = red[0];
}

__global__ void k_red_sum(int nblocks) {
    __shared__ float red[256];
    int t = threadIdx.x;
    float s = 0.f;
    for (int i = t; i < nblocks; i += 256) s += g_partsum[i];
    red[t] = s; __syncthreads();
    for (int st = 128; st; st >>= 1) {
        if (t < st) red[t] += red[t + st];
        __syncthreads();
    }
    if (t == 0) g_lse = g_gmax + logf(red[0]);
}

__global__ void k_sub(float* __restrict__ logits) {
    int i = blockIdx.x * blockDim.x + threadIdx.x;
    if (i < VOCAB) logits[i] -= g_lse;
}

// ---------------------------------------------------------------------------
extern "C" void kernel_launch(void* const* d_in, const int* in_sizes, int n_in,
                              void* d_out, int out_size) {
    const int*   token  = (const int*)  d_in[0];
    const float* hidden = (const float*)d_in[1];
    const float* enc    = (const float*)d_in[2];
    const float* emb    = (const float*)d_in[3];
    const float* attn_w = (const float*)d_in[4];
    const float* attn_b = (const float*)d_in[5];
    const float* comb_w = (const float*)d_in[6];
    const float* comb_b = (const float*)d_in[7];
    const float* g_wih  = (const float*)d_in[8];
    const float* g_whh  = (const float*)d_in[9];
    const float* g_bih  = (const float*)d_in[10];
    const float* g_bhh  = (const float*)d_in[11];
    const float* out_w  = (const float*)d_in[12];
    const float* out_b  = (const float*)d_in[13];

    float* out        = (float*)d_out;
    float* out_logits = out;                    // [0, VOCAB)
    float* out_hidden = out + VOCAB;            // [VOCAB, VOCAB+1024)
    float* out_attnw  = out + VOCAB + NLAYERS * HIDDEN;  // [.., +256)

    float* g_attn_logits_p; cudaGetSymbolAddress((void**)&g_attn_logits_p, g_attn_logits);
    float* g_x_p;           cudaGetSymbolAddress((void**)&g_x_p, g_x);
    float* g_attn_in_p;     cudaGetSymbolAddress((void**)&g_attn_in_p, g_attn_in);
    float* g_comb_in_p;     cudaGetSymbolAddress((void**)&g_comb_in_p, g_comb_in);

    // 1) embed + attn_in
    k_prep<<<1, 256>>>(token, hidden, emb);
    // 2) attention logits: 256 rows x 512 cols
    k_matvec<512, false><<<32, 256>>>(attn_w, attn_b, g_attn_in_p, g_attn_logits_p, MAXLEN);
    // 3) softmax + attn_applied + comb_in
    k_attn_post<<<1, 256>>>(enc, out_attnw);
    // 4) comb + relu: 256 rows x 512 cols -> g_x
    k_matvec<512, true><<<32, 256>>>(comb_w, comb_b, g_comb_in_p, g_x_p, HIDDEN);
    // 5) 4 GRU layers
    for (int l = 0; l < NLAYERS; l++) {
        k_gru_mv<<<192, 256>>>(g_wih, g_whh, g_bih, g_bhh, hidden, l);
        k_gru_combine<<<1, 256>>>(hidden, l, out_hidden);
    }
    // 6) vocab logits + per-block max
    int nb = (VOCAB + 7) / 8;                  // 6283 blocks, warp per row
    k_logits<<<nb, 256>>>(out_w, out_b, out_logits);
    // 7) log-softmax tail
    k_red_max<<<1, 256>>>(nb);
    k_sumexp<<<148, 256>>>(out_logits);
    k_red_sum<<<1, 256>>>(148);
    k_sub<<<(VOCAB + 255) / 256, 256>>>(out_logits);
}

// round 4
// speedup vs baseline: 1.1835x; 1.1835x over previous
#include <cuda_runtime.h>
#include <math.h>

#define HIDDEN   256
#define MAXLEN   256
#define NLAYERS  4
#define VOCAB    50257

// ---------------- scratch (device globals) ---------------------------------
__device__ int   g_c[8];            // barriers: 0=B1 attn, 1=B2 applied+embed, 2=BX0 comb, 3=BGH, 4..7=Bgi[l]
__device__ int   g_ct;              // tail barrier counter
__device__ float g_attnlog[MAXLEN];
__device__ float g_cin[2 * HIDDEN]; // [embedded | attn_applied]
__device__ float g_x[HIDDEN];       // comb output (GRU layer-0 input)
__device__ float g_xf[HIDDEN];      // final GRU output (logits input)
__device__ float g_gh[NLAYERS * 3 * HIDDEN];
__device__ float g_gi[NLAYERS * 3 * HIDDEN];
__device__ float g_part[64];

__device__ __forceinline__ float warp_sum(float s) {
#pragma unroll
    for (int o = 16; o; o >>= 1) s += __shfl_down_sync(0xffffffffu, s, o);
    return s;
}
__device__ __forceinline__ float dot4(float4 a, float4 b) {
    return a.x * b.x + a.y * b.y + a.z * b.z + a.w * b.w;
}
__device__ __forceinline__ void bar_spin(int* c, int target) {
    while (*((volatile int*)c) < target) { }
}

// ======================= MEGA KERNEL (417 blocks x 256) =====================
// blocks 0..31  : attn logits -> softmax -> applied -> comb, then GRU
// block  32     : embedding write + tail-counter reset, then GRU
// blocks 33..95 : gh rows, then GRU
// blocks 96..416: gh rows only
__global__ void __launch_bounds__(256) k_mega(
    const int* __restrict__ token,  const float* __restrict__ hidden,
    const float* __restrict__ enc,  const float* __restrict__ emb,
    const float* __restrict__ attn_w, const float* __restrict__ attn_b,
    const float* __restrict__ comb_w, const float* __restrict__ comb_b,
    const float* __restrict__ wih,  const float* __restrict__ whh,
    const float* __restrict__ bih,  const float* __restrict__ bhh,
    float* __restrict__ out_attnw,  float* __restrict__ out_hidden)
{
    __shared__ float sh[2 * HIDDEN];   // [0:256) reduce scratch / x ; [256:512) softmax weights
    const int blk = blockIdx.x, tid = threadIdx.x;
    const int w = tid >> 5, lane = tid & 31;

    if (blk == 32) {
        // embedding + reset tail counter for next replay; then join GRU
        if (tid == 0) g_ct = 0;
        int tok = token[0];
        float e = __ldg(&emb[(size_t)tok * HIDDEN + tid]);
        __stcg(&g_cin[tid], e);
        __threadfence();
        __syncthreads();
        if (tid == 0) atomicAdd(&g_c[1], 1);     // B2 arrival (embed part)
    } else if (blk >= 33) {
        // ---- gh rows: row = (blk-33)*8 + w in [0, 3072) ----
        int row = (blk - 33) * 8 + w;
        int l = row / (3 * HIDDEN), rr = row % (3 * HIDDEN);
        const float4* W = (const float4*)(whh + ((size_t)l * 3 * HIDDEN + rr) * HIDDEN);
        const float4* V = (const float4*)(hidden + l * HIDDEN);
        float s = 0.f;
#pragma unroll
        for (int c = 0; c < 2; c++)
            s += dot4(__ldg(&W[lane + c * 32]), __ldg(&V[lane + c * 32]));
        s = warp_sum(s);
        if (lane == 0) __stcg(&g_gh[row], s + __ldg(&bhh[l * 3 * HIDDEN + rr]));
        __threadfence();
        __syncthreads();
        if (tid == 0) atomicAdd(&g_c[3], 1);     // BGH arrival
        if (blk >= 96) return;
        // blocks 33..95 fall through to GRU
    } else {
        // ============ blocks 0..31: attention front-end ============
        int row = blk * 8 + w;                   // 0..255
        int tok = token[0];
        {
            const float4* W = (const float4*)(attn_w + (size_t)row * 2 * HIDDEN);
            float s = 0.f;
#pragma unroll
            for (int c = 0; c < 4; c++) {
                float4 a = __ldg(&W[lane + c * 32]);
                int base = (lane + c * 32) * 4;  // element idx 0..511
                float4 v = (base < HIDDEN)
                    ? __ldg((const float4*)&emb[(size_t)tok * HIDDEN + base])
                    : __ldg((const float4*)&hidden[base - HIDDEN]);
                s += dot4(a, v);
            }
            s = warp_sum(s);
            if (lane == 0) __stcg(&g_attnlog[row], s + __ldg(&attn_b[row]));
        }
        __threadfence();
        __syncthreads();
        if (tid == 0) { atomicAdd(&g_c[0], 1); bar_spin(&g_c[0], 32); }
        __syncthreads();
        __threadfence();

        // ---- softmax (redundant per block) ----
        float v = __ldcg(&g_attnlog[tid]);
        sh[tid] = v; __syncthreads();
        for (int s2 = 128; s2; s2 >>= 1) {
            if (tid < s2) sh[tid] = fmaxf(sh[tid], sh[tid + s2]);
            __syncthreads();
        }
        float m = sh[0]; __syncthreads();
        float e = expf(v - m);
        sh[tid] = e; __syncthreads();
        for (int s2 = 128; s2; s2 >>= 1) {
            if (tid < s2) sh[tid] += sh[tid + s2];
            __syncthreads();
        }
        float wgt = e / sh[0]; __syncthreads();
        sh[HIDDEN + tid] = wgt;
        if (blk == 0) out_attnw[tid] = wgt;
        __syncthreads();

        // ---- attn_applied for t = blk*8 + w ----
        {
            int t = blk * 8 + w;
            float a = 0.f;
#pragma unroll
            for (int j = 0; j < 8; j++) {
                int l2 = lane + j * 32;
                a += sh[HIDDEN + l2] * __ldg(&enc[l2 * HIDDEN + t]);
            }
            a = warp_sum(a);
            if (lane == 0) __stcg(&g_cin[HIDDEN + t], a);
        }
        __threadfence();
        __syncthreads();
        if (tid == 0) { atomicAdd(&g_c[1], 1); bar_spin(&g_c[1], 33); }
        __syncthreads();
        __threadfence();

        // ---- comb + relu: row = blk*8 + w ----
        {
            const float4* W = (const float4*)(comb_w + (size_t)row * 2 * HIDDEN);
            float s = 0.f;
#pragma unroll
            for (int c = 0; c < 4; c++) {
                float4 a  = __ldg(&W[lane + c * 32]);
                float4 vv = __ldcg((const float4*)&g_cin[(lane + c * 32) * 4]);
                s += dot4(a, vv);
            }
            s = warp_sum(s);
            if (lane == 0) __stcg(&g_x[row], fmaxf(s + __ldg(&comb_b[row]), 0.f));
        }
        __threadfence();
        __syncthreads();
        if (tid == 0) atomicAdd(&g_c[2], 1);     // BX0 arrival
    }

    // ================= GRU: blocks 0..95 (96 blocks, rows 0..767) ==========
    if (tid == 0) bar_spin(&g_c[2], 32);         // wait comb done
    __syncthreads();
    __threadfence();
    sh[tid] = __ldcg(&g_x[tid]);                 // x -> smem
    __syncthreads();

    for (int l = 0; l < NLAYERS; l++) {
        // gi row = blk*8 + w in [0,768)
        int r = blk * 8 + w;
        {
            const float4* W = (const float4*)(wih + ((size_t)l * 3 * HIDDEN + r) * HIDDEN);
            const float4* V = (const float4*)sh;
            float s = 0.f;
#pragma unroll
            for (int c = 0; c < 2; c++)
                s += dot4(__ldg(&W[lane + c * 32]), V[lane + c * 32]);
            s = warp_sum(s);
            if (lane == 0) __stcg(&g_gi[l * 3 * HIDDEN + r], s + __ldg(&bih[l * 3 * HIDDEN + r]));
        }
        __threadfence();
        __syncthreads();
        if (tid == 0) {
            atomicAdd(&g_c[4 + l], 1);
            if (l == 0) bar_spin(&g_c[3], 384);  // gh must be complete
            bar_spin(&g_c[4 + l], 96);
        }
        __syncthreads();
        __threadfence();

        // redundant elementwise combine, t = tid
        const float* gi = g_gi + l * 3 * HIDDEN;
        const float* gh = g_gh + l * 3 * HIDDEN;
        float ir = __ldcg(&gi[tid]),        iz = __ldcg(&gi[HIDDEN + tid]),  in_ = __ldcg(&gi[2 * HIDDEN + tid]);
        float hr = __ldcg(&gh[tid]),        hz = __ldcg(&gh[HIDDEN + tid]),  hn  = __ldcg(&gh[2 * HIDDEN + tid]);
        float rg = 1.f / (1.f + expf(-(ir + hr)));
        float zg = 1.f / (1.f + expf(-(iz + hz)));
        float ng = tanhf(in_ + rg * hn);
        float hp = __ldg(&hidden[l * HIDDEN + tid]);
        float h  = (1.f - zg) * ng + zg * hp;
        __syncthreads();                          // all done reading sh (x)
        sh[tid] = h;
        if (blk == 0) out_hidden[l * HIDDEN + tid] = h;
        __syncthreads();
    }
    if (blk == 0) __stcg(&g_xf[tid], sh[tid]);
}

// ======================= vocab logits: 4 rows per warp ======================
__global__ void __launch_bounds__(256) k_logits(
    const float* __restrict__ out_w, const float* __restrict__ out_b,
    float* __restrict__ logits)
{
    __shared__ float sx[HIDDEN];
    int tid = threadIdx.x, w = tid >> 5, lane = tid & 31;
    sx[tid] = __ldcg(&g_xf[tid]);
    __syncthreads();
    const float4* V = (const float4*)sx;
    float4 v0 = V[lane], v1 = V[lane + 32];
    int r0 = (blockIdx.x * 8 + w) * 4;
    float s0 = 0.f, s1 = 0.f, s2 = 0.f, s3 = 0.f;
    if (r0 + 0 < VOCAB) { const float4* W = (const float4*)(out_w + (size_t)(r0 + 0) * HIDDEN); s0 = dot4(__ldg(&W[lane]), v0) + dot4(__ldg(&W[lane + 32]), v1); }
    if (r0 + 1 < VOCAB) { const float4* W = (const float4*)(out_w + (size_t)(r0 + 1) * HIDDEN); s1 = dot4(__ldg(&W[lane]), v0) + dot4(__ldg(&W[lane + 32]), v1); }
    if (r0 + 2 < VOCAB) { const float4* W = (const float4*)(out_w + (size_t)(r0 + 2) * HIDDEN); s2 = dot4(__ldg(&W[lane]), v0) + dot4(__ldg(&W[lane + 32]), v1); }
    if (r0 + 3 < VOCAB) { const float4* W = (const float4*)(out_w + (size_t)(r0 + 3) * HIDDEN); s3 = dot4(__ldg(&W[lane]), v0) + dot4(__ldg(&W[lane + 32]), v1); }
#pragma unroll
    for (int o = 16; o; o >>= 1) {
        s0 += __shfl_down_sync(0xffffffffu, s0, o);
        s1 += __shfl_down_sync(0xffffffffu, s1, o);
        s2 += __shfl_down_sync(0xffffffffu, s2, o);
        s3 += __shfl_down_sync(0xffffffffu, s3, o);
    }
    if (lane == 0) {
        if (r0 + 0 < VOCAB) logits[r0 + 0] = s0 + __ldg(&out_b[r0 + 0]);
        if (r0 + 1 < VOCAB) logits[r0 + 1] = s1 + __ldg(&out_b[r0 + 1]);
        if (r0 + 2 < VOCAB) logits[r0 + 2] = s2 + __ldg(&out_b[r0 + 2]);
        if (r0 + 3 < VOCAB) logits[r0 + 3] = s3 + __ldg(&out_b[r0 + 3]);
    }
}

// ============== fused log-softmax tail (64 blocks, 1 barrier) ===============
__global__ void __launch_bounds__(256) k_tail(float* __restrict__ logits)
{
    __shared__ float red[256];
    int tid = threadIdx.x, blk = blockIdx.x;
    float s = 0.f;
    for (int i = blk * 256 + tid; i < VOCAB; i += 64 * 256) s += expf(logits[i]);
    red[tid] = s; __syncthreads();
    for (int st = 128; st; st >>= 1) {
        if (tid < st) red[tid] += red[tid + st];
        __syncthreads();
    }
    if (tid == 0) {
        __stcg(&g_part[blk], red[0]);
        __threadfence();
        atomicAdd(&g_ct, 1);
        bar_spin(&g_ct, 64);
        __threadfence();
        float tot = 0.f;
        for (int i = 0; i < 64; i++) tot += __ldcg(&g_part[i]);
        red[0] = logf(tot);
    }
    __syncthreads();
    float lse = red[0];
    for (int i = blk * 256 + tid; i < VOCAB; i += 64 * 256) logits[i] -= lse;
    if (blk == 0 && tid == 0) {
#pragma unroll
        for (int i = 0; i < 8; i++) g_c[i] = 0;   // reset mega barriers for next replay
    }
}

// ---------------------------------------------------------------------------
extern "C" void kernel_launch(void* const* d_in, const int* in_sizes, int n_in,
                              void* d_out, int out_size) {
    const int*   token  = (const int*)  d_in[0];
    const float* hidden = (const float*)d_in[1];
    const float* enc    = (const float*)d_in[2];
    const float* emb    = (const float*)d_in[3];
    const float* attn_w = (const float*)d_in[4];
    const float* attn_b = (const float*)d_in[5];
    const float* comb_w = (const float*)d_in[6];
    const float* comb_b = (const float*)d_in[7];
    const float* g_wih  = (const float*)d_in[8];
    const float* g_whh  = (const float*)d_in[9];
    const float* g_bih  = (const float*)d_in[10];
    const float* g_bhh  = (const float*)d_in[11];
    const float* out_w  = (const float*)d_in[12];
    const float* out_b  = (const float*)d_in[13];

    float* out        = (float*)d_out;
    float* out_logits = out;
    float* out_hidden = out + VOCAB;
    float* out_attnw  = out + VOCAB + NLAYERS * HIDDEN;

    k_mega<<<417, 256>>>(token, hidden, enc, emb, attn_w, attn_b, comb_w, comb_b,
                         g_wih, g_whh, g_bih, g_bhh, out_attnw, out_hidden);
    k_logits<<<(VOCAB + 31) / 32, 256>>>(out_w, out_b, out_logits);
    k_tail<<<64, 256>>>(out_logits);
}